// round 5
// baseline (speedup 1.0000x reference)
#include <cuda_runtime.h>
#include <cuda_bf16.h>
#include <cstdint>
#include <cstddef>

#define NN 50000
#define NE 600000
#define D 128
#define BN_EPS 1e-5f

// ---------------- scratch (device globals) -------------------------------------
__device__ float g_h[NN * D];        // embed output (layer-0 agg input)
__device__ float g_agg[NN * D];
__device__ float g_mid[NN * 2 * D];
__device__ float g_h2[NN * D];       // pre-BN output of each layer
__device__ float g_sum[D];
__device__ float g_sumsq[D];
__device__ float g_bns[D];           // BN scale per column
__device__ float g_bnt[D];           // BN shift per column
// CSR structures
__device__ int   g_cnt[NN];
__device__ int   g_rowstart[NN + 1];
__device__ int   g_cursor[NN];
__device__ int   g_edges[NE];        // src | (combo << 16)
__device__ float g_eec[24 * D];

// ---------------- input embedding ---------------------------------------------
__global__ void embed_kernel(const int* __restrict__ x,
                             const float* __restrict__ atom,
                             const float* __restrict__ chir,
                             const float* __restrict__ hyb) {
    int t = blockIdx.x * blockDim.x + threadIdx.x;
    int node = t >> 5, lane = t & 31;
    if (node >= NN) return;
    int x0 = x[node * 3 + 0];
    int x1 = x[node * 3 + 1];
    int x2 = x[node * 3 + 2];
    float4 a = ((const float4*)(atom + (size_t)x0 * D))[lane];
    float4 c = ((const float4*)(chir + (size_t)x1 * D))[lane];
    float4 y = ((const float4*)(hyb  + (size_t)x2 * D))[lane];
    ((float4*)g_h)[(size_t)node * 32 + lane] =
        make_float4(a.x + c.x + y.x, a.y + c.y + y.y,
                    a.z + c.z + y.z, a.w + c.w + y.w);
}

// ---------------- CSR build ----------------------------------------------------
__global__ void count_kernel(const int* __restrict__ ei) {
    int e = blockIdx.x * blockDim.x + threadIdx.x;
    if (e >= NE) return;
    atomicAdd(&g_cnt[ei[NE + e]], 1);
}

__global__ void scan_kernel() {
    __shared__ int warpsum[32];
    __shared__ int carry;
    int lane = threadIdx.x & 31, wid = threadIdx.x >> 5;
    if (threadIdx.x == 0) carry = 0;
    __syncthreads();
    for (int base = 0; base < NN; base += 1024) {
        int i = base + threadIdx.x;
        int v = (i < NN) ? g_cnt[i] : 0;
        int xs = v;
#pragma unroll
        for (int off = 1; off < 32; off <<= 1) {
            int t = __shfl_up_sync(0xffffffff, xs, off);
            if (lane >= off) xs += t;
        }
        if (lane == 31) warpsum[wid] = xs;
        __syncthreads();
        if (wid == 0) {
            int w = warpsum[lane];
#pragma unroll
            for (int off = 1; off < 32; off <<= 1) {
                int t = __shfl_up_sync(0xffffffff, w, off);
                if (lane >= off) w += t;
            }
            warpsum[lane] = w;
        }
        __syncthreads();
        int wpre = (wid > 0) ? warpsum[wid - 1] : 0;
        int incl = xs + wpre;
        int excl = incl - v + carry;
        if (i < NN) { g_rowstart[i] = excl; g_cursor[i] = excl; }
        __syncthreads();
        if (threadIdx.x == 1023) carry += incl;
        __syncthreads();
    }
    if (threadIdx.x == 0) g_rowstart[NN] = carry;
}

__global__ void fill_kernel(const int* __restrict__ ei,
                            const int* __restrict__ ea) {
    int e = blockIdx.x * blockDim.x + threadIdx.x;
    if (e >= NE) return;
    int dst = ei[NE + e];
    int pos = atomicAdd(&g_cursor[dst], 1);
    int cb = ea[2 * e] * 4 + ea[2 * e + 1];
    g_edges[pos] = ei[e] | (cb << 16);
}

// ---------------- per-layer edge-combo table ------------------------------------
__global__ void eec_kernel(const float* __restrict__ e1l,
                           const float* __restrict__ e2l) {
    int cb = blockIdx.x;
    int lane = threadIdx.x;
    int a0 = cb >> 2, a1 = cb & 3;
    float4 v1 = ((const float4*)(e1l + (size_t)a0 * D))[lane];
    float4 v2 = ((const float4*)(e2l + (size_t)a1 * D))[lane];
    ((float4*)g_eec)[cb * 32 + lane] =
        make_float4(v1.x + v2.x, v1.y + v2.y, v1.z + v2.z, v1.w + v2.w);
}

// ---------------- BN scale/shift prep: s = g*rsqrt(var+eps), t = b - mu*s ------
__global__ void bnprep_kernel(const float* __restrict__ gamma,
                              const float* __restrict__ beta) {
    int c = threadIdx.x;
    const float inv = 1.0f / (float)NN;
    float mean = g_sum[c] * inv;
    float var = g_sumsq[c] * inv - mean * mean;
    float s = gamma[c] * rsqrtf(var + BN_EPS);
    g_bns[c] = s;
    g_bnt[c] = beta[c] - mean * s;
}

// ---------------- gather-aggregate with fused BN+ReLU on source ----------------
__global__ void agg_kernel(const float* __restrict__ h, int bn) {
    int t = blockIdx.x * blockDim.x + threadIdx.x;
    int n = t >> 5, lane = t & 31;
    if (n >= NN) return;
    float4 s4 = make_float4(1.f, 1.f, 1.f, 1.f);
    float4 t4 = make_float4(0.f, 0.f, 0.f, 0.f);
    if (bn) {
        s4 = ((const float4*)g_bns)[lane];
        t4 = ((const float4*)g_bnt)[lane];
    }
    int beg = g_rowstart[n], end = g_rowstart[n + 1];
    float4 acc = make_float4(0.f, 0.f, 0.f, 0.f);
    int i = beg;
    for (; i + 1 < end; i += 2) {
        int p0 = g_edges[i];
        int p1 = g_edges[i + 1];
        float4 a = ((const float4*)h)[(size_t)(p0 & 0xFFFF) * 32 + lane];
        float4 b = ((const float4*)h)[(size_t)(p1 & 0xFFFF) * 32 + lane];
        float4 ea0 = ((const float4*)g_eec)[(p0 >> 16) * 32 + lane];
        float4 eb0 = ((const float4*)g_eec)[(p1 >> 16) * 32 + lane];
        if (bn) {
            a.x = fmaxf(fmaf(s4.x, a.x, t4.x), 0.f);
            a.y = fmaxf(fmaf(s4.y, a.y, t4.y), 0.f);
            a.z = fmaxf(fmaf(s4.z, a.z, t4.z), 0.f);
            a.w = fmaxf(fmaf(s4.w, a.w, t4.w), 0.f);
            b.x = fmaxf(fmaf(s4.x, b.x, t4.x), 0.f);
            b.y = fmaxf(fmaf(s4.y, b.y, t4.y), 0.f);
            b.z = fmaxf(fmaf(s4.z, b.z, t4.z), 0.f);
            b.w = fmaxf(fmaf(s4.w, b.w, t4.w), 0.f);
        }
        acc.x += (a.x + ea0.x) + (b.x + eb0.x);
        acc.y += (a.y + ea0.y) + (b.y + eb0.y);
        acc.z += (a.z + ea0.z) + (b.z + eb0.z);
        acc.w += (a.w + ea0.w) + (b.w + eb0.w);
    }
    if (i < end) {
        int p0 = g_edges[i];
        float4 a = ((const float4*)h)[(size_t)(p0 & 0xFFFF) * 32 + lane];
        float4 ea0 = ((const float4*)g_eec)[(p0 >> 16) * 32 + lane];
        if (bn) {
            a.x = fmaxf(fmaf(s4.x, a.x, t4.x), 0.f);
            a.y = fmaxf(fmaf(s4.y, a.y, t4.y), 0.f);
            a.z = fmaxf(fmaf(s4.z, a.z, t4.z), 0.f);
            a.w = fmaxf(fmaf(s4.w, a.w, t4.w), 0.f);
        }
        acc.x += a.x + ea0.x;
        acc.y += a.y + ea0.y;
        acc.z += a.z + ea0.z;
        acc.w += a.w + ea0.w;
    }
    ((float4*)g_agg)[(size_t)n * 32 + lane] = acc;
}

// ---------------- final BN apply (no relu) --------------------------------------
__global__ void bn_final_kernel(const float* __restrict__ h2,
                                float* __restrict__ outp) {
    int t = blockIdx.x * blockDim.x + threadIdx.x;
    int node = t >> 5, lane = t & 31;
    if (node >= NN) return;
    float4 s4 = ((const float4*)g_bns)[lane];
    float4 t4 = ((const float4*)g_bnt)[lane];
    float4 v = ((const float4*)h2)[(size_t)node * 32 + lane];
    ((float4*)outp)[(size_t)node * 32 + lane] =
        make_float4(fmaf(s4.x, v.x, t4.x), fmaf(s4.y, v.y, t4.y),
                    fmaf(s4.z, v.z, t4.z), fmaf(s4.w, v.w, t4.w));
}

__global__ void zero_stats_kernel() {
    g_sum[threadIdx.x] = 0.f;
    g_sumsq[threadIdx.x] = 0.f;
}

// ---------------- 3xTF32 GEMM, register-prefetch pipelined, optional stats ------
__device__ __forceinline__ uint32_t tf32_rna_u(float x) {
    uint32_t u;
    asm("cvt.rna.tf32.f32 %0, %1;" : "=r"(u) : "f"(x));
    return u;
}

#define MMA_TF32(acc, a, b)                                              \
    asm volatile(                                                        \
        "mma.sync.aligned.m16n8k8.row.col.f32.tf32.tf32.f32 "            \
        "{%0,%1,%2,%3}, {%4,%5,%6,%7}, {%8,%9}, {%0,%1,%2,%3};\n"        \
        : "+f"(acc[0]), "+f"(acc[1]), "+f"(acc[2]), "+f"(acc[3])         \
        : "r"(a[0]), "r"(a[1]), "r"(a[2]), "r"(a[3]),                    \
          "r"(b[0]), "r"(b[1]))

#define SM_ASZ (128 * 36)
#define SM_BSZ (32 * 132)
#define SMEM_FLOATS (2 * SM_ASZ + 2 * SM_BSZ)

__device__ __forceinline__ void split_store(float4 v, float* hi, float* lo) {
    uint32_t hx = tf32_rna_u(v.x), hy = tf32_rna_u(v.y),
             hz = tf32_rna_u(v.z), hw = tf32_rna_u(v.w);
    uint32_t lx = tf32_rna_u(v.x - __uint_as_float(hx));
    uint32_t ly = tf32_rna_u(v.y - __uint_as_float(hy));
    uint32_t lz = tf32_rna_u(v.z - __uint_as_float(hz));
    uint32_t lw = tf32_rna_u(v.w - __uint_as_float(hw));
    *(float4*)hi = make_float4(__uint_as_float(hx), __uint_as_float(hy),
                               __uint_as_float(hz), __uint_as_float(hw));
    *(float4*)lo = make_float4(__uint_as_float(lx), __uint_as_float(ly),
                               __uint_as_float(lz), __uint_as_float(lw));
}

__global__ __launch_bounds__(256) void gemm_tf32x3_kernel(
    const float* __restrict__ A, const float* __restrict__ B,
    const float* __restrict__ bias, float* __restrict__ C,
    int M, int N, int K, int relu, int do_stats) {
    extern __shared__ float sm[];
    float* As_hi = sm;
    float* As_lo = sm + SM_ASZ;
    float* Bs_hi = sm + 2 * SM_ASZ;
    float* Bs_lo = sm + 2 * SM_ASZ + SM_BSZ;

    const int tid  = threadIdx.x;
    const int warp = tid >> 5, lane = tid & 31;
    const int gid  = lane >> 2;
    const int tig  = lane & 3;
    const int wm   = (warp & 3) * 32;
    const int wn   = (warp >> 2) * 64;
    const int m0   = blockIdx.y * 128;
    const int n0b  = blockIdx.x * 128;

    float acc[2][8][4];
#pragma unroll
    for (int mi = 0; mi < 2; mi++)
#pragma unroll
        for (int ni = 0; ni < 8; ni++)
#pragma unroll
            for (int q = 0; q < 4; q++) acc[mi][ni][q] = 0.f;

    const int ar = tid >> 3, ac = (tid & 7) << 2;
    const int br = tid >> 5, bc = (tid & 31) << 2;

    // prologue: prefetch chunk 0
    float4 ra[4], rb[4];
#pragma unroll
    for (int i = 0; i < 4; i++) {
        int r = ar + i * 32;
        ra[i] = make_float4(0.f, 0.f, 0.f, 0.f);
        if (m0 + r < M)
            ra[i] = *(const float4*)(A + (size_t)(m0 + r) * K + ac);
    }
#pragma unroll
    for (int i = 0; i < 4; i++)
        rb[i] = *(const float4*)(B + (size_t)(br + i * 8) * N + n0b + bc);

    for (int k0 = 0; k0 < K; k0 += 32) {
        // split regs into smem
#pragma unroll
        for (int i = 0; i < 4; i++) {
            int r = ar + i * 32;
            split_store(ra[i], &As_hi[r * 36 + ac], &As_lo[r * 36 + ac]);
        }
#pragma unroll
        for (int i = 0; i < 4; i++) {
            int r = br + i * 8;
            split_store(rb[i], &Bs_hi[r * 132 + bc], &Bs_lo[r * 132 + bc]);
        }
        __syncthreads();

        // prefetch next chunk (overlaps with MMA below)
        if (k0 + 32 < K) {
            int kn = k0 + 32;
#pragma unroll
            for (int i = 0; i < 4; i++) {
                int r = ar + i * 32;
                ra[i] = make_float4(0.f, 0.f, 0.f, 0.f);
                if (m0 + r < M)
                    ra[i] = *(const float4*)(A + (size_t)(m0 + r) * K + kn + ac);
            }
#pragma unroll
            for (int i = 0; i < 4; i++)
                rb[i] = *(const float4*)(B + (size_t)(kn + br + i * 8) * N + n0b + bc);
        }

#pragma unroll
        for (int ks = 0; ks < 4; ks++) {
            const int kk = ks * 8;
            uint32_t ah[2][4], al[2][4], bh[8][2], bl[8][2];
#pragma unroll
            for (int mi = 0; mi < 2; mi++) {
                int r0 = wm + mi * 16 + gid;
                ah[mi][0] = __float_as_uint(As_hi[r0 * 36 + kk + tig]);
                ah[mi][1] = __float_as_uint(As_hi[(r0 + 8) * 36 + kk + tig]);
                ah[mi][2] = __float_as_uint(As_hi[r0 * 36 + kk + tig + 4]);
                ah[mi][3] = __float_as_uint(As_hi[(r0 + 8) * 36 + kk + tig + 4]);
                al[mi][0] = __float_as_uint(As_lo[r0 * 36 + kk + tig]);
                al[mi][1] = __float_as_uint(As_lo[(r0 + 8) * 36 + kk + tig]);
                al[mi][2] = __float_as_uint(As_lo[r0 * 36 + kk + tig + 4]);
                al[mi][3] = __float_as_uint(As_lo[(r0 + 8) * 36 + kk + tig + 4]);
            }
#pragma unroll
            for (int ni = 0; ni < 8; ni++) {
                int c0 = wn + ni * 8 + gid;
                bh[ni][0] = __float_as_uint(Bs_hi[(kk + tig) * 132 + c0]);
                bh[ni][1] = __float_as_uint(Bs_hi[(kk + tig + 4) * 132 + c0]);
                bl[ni][0] = __float_as_uint(Bs_lo[(kk + tig) * 132 + c0]);
                bl[ni][1] = __float_as_uint(Bs_lo[(kk + tig + 4) * 132 + c0]);
            }
#pragma unroll
            for (int mi = 0; mi < 2; mi++)
#pragma unroll
                for (int ni = 0; ni < 8; ni++) {
                    MMA_TF32(acc[mi][ni], al[mi], bh[ni]);
                    MMA_TF32(acc[mi][ni], ah[mi], bl[ni]);
                    MMA_TF32(acc[mi][ni], ah[mi], bh[ni]);
                }
        }
        __syncthreads();
    }

    // epilogue: bias (+relu) store, plus optional per-column stats
    float ls[16], ls2[16];
#pragma unroll
    for (int j = 0; j < 16; j++) { ls[j] = 0.f; ls2[j] = 0.f; }

#pragma unroll
    for (int mi = 0; mi < 2; mi++) {
        int r0 = m0 + wm + mi * 16 + gid;
#pragma unroll
        for (int ni = 0; ni < 8; ni++) {
            int gc = n0b + wn + ni * 8 + 2 * tig;
            float bv0 = bias[gc], bv1 = bias[gc + 1];
            float v0 = acc[mi][ni][0] + bv0;
            float v1 = acc[mi][ni][1] + bv1;
            float v2 = acc[mi][ni][2] + bv0;
            float v3 = acc[mi][ni][3] + bv1;
            if (relu) {
                v0 = fmaxf(v0, 0.f); v1 = fmaxf(v1, 0.f);
                v2 = fmaxf(v2, 0.f); v3 = fmaxf(v3, 0.f);
            }
            bool ok0 = (r0 < M), ok1 = (r0 + 8 < M);
            if (ok0)
                *(float2*)(C + (size_t)r0 * N + gc) = make_float2(v0, v1);
            if (ok1)
                *(float2*)(C + (size_t)(r0 + 8) * N + gc) = make_float2(v2, v3);
            if (do_stats) {
                if (ok0) {
                    ls[ni * 2]     += v0; ls2[ni * 2]     += v0 * v0;
                    ls[ni * 2 + 1] += v1; ls2[ni * 2 + 1] += v1 * v1;
                }
                if (ok1) {
                    ls[ni * 2]     += v2; ls2[ni * 2]     += v2 * v2;
                    ls[ni * 2 + 1] += v3; ls2[ni * 2 + 1] += v3 * v3;
                }
            }
        }
    }

    if (do_stats) {
        // reduce over gid (lanes stride 4 share the same columns)
#pragma unroll
        for (int j = 0; j < 16; j++) {
#pragma unroll
            for (int off = 4; off < 32; off <<= 1) {
                ls[j]  += __shfl_xor_sync(0xffffffff, ls[j], off);
                ls2[j] += __shfl_xor_sync(0xffffffff, ls2[j], off);
            }
        }
        float* cs  = sm;        // reuse smem (free after last __syncthreads)
        float* cs2 = sm + 128;
        if (tid < 128) { cs[tid] = 0.f; cs2[tid] = 0.f; }
        __syncthreads();
        if (lane < 4) {
#pragma unroll
            for (int ni = 0; ni < 8; ni++) {
                int c0 = wn + ni * 8 + 2 * lane;  // lane==tig here
                atomicAdd(&cs[c0],      ls[ni * 2]);
                atomicAdd(&cs2[c0],     ls2[ni * 2]);
                atomicAdd(&cs[c0 + 1],  ls[ni * 2 + 1]);
                atomicAdd(&cs2[c0 + 1], ls2[ni * 2 + 1]);
            }
        }
        __syncthreads();
        if (tid < 128) {
            atomicAdd(&g_sum[tid],   cs[tid]);
            atomicAdd(&g_sumsq[tid], cs2[tid]);
        }
    }
}

// ---------------- launch --------------------------------------------------------
extern "C" void kernel_launch(void* const* d_in, const int* in_sizes, int n_in,
                              void* d_out, int out_size) {
    const int*   x     = (const int*)d_in[0];
    const int*   ei    = (const int*)d_in[1];
    const int*   ea    = (const int*)d_in[2];
    const float* atom  = (const float*)d_in[3];
    const float* chir  = (const float*)d_in[4];
    const float* hyb   = (const float*)d_in[5];
    const float* e1    = (const float*)d_in[6];
    const float* e2    = (const float*)d_in[7];
    const float* W1    = (const float*)d_in[8];
    const float* b1    = (const float*)d_in[9];
    const float* W2    = (const float*)d_in[10];
    const float* b2    = (const float*)d_in[11];
    const float* gamma = (const float*)d_in[12];
    const float* beta  = (const float*)d_in[13];
    float* out = (float*)d_out;

    float *p_h, *p_agg, *p_mid, *p_h2;
    int* p_cnt;
    cudaGetSymbolAddress((void**)&p_h,   g_h);
    cudaGetSymbolAddress((void**)&p_agg, g_agg);
    cudaGetSymbolAddress((void**)&p_mid, g_mid);
    cudaGetSymbolAddress((void**)&p_h2,  g_h2);
    cudaGetSymbolAddress((void**)&p_cnt, g_cnt);

    const size_t smbytes = SMEM_FLOATS * sizeof(float);
    cudaFuncSetAttribute(gemm_tf32x3_kernel,
                         cudaFuncAttributeMaxDynamicSharedMemorySize,
                         (int)smbytes);

    const int TPB = 256;
    const int node_blocks = (NN * 32 + TPB - 1) / TPB;
    const int edge_blocks = (NE + TPB - 1) / TPB;
    const int mrows = (NN + 127) / 128;

    // CSR build (layer-invariant)
    cudaMemsetAsync(p_cnt, 0, NN * sizeof(int));
    count_kernel<<<edge_blocks, TPB>>>(ei);
    scan_kernel<<<1, 1024>>>();
    fill_kernel<<<edge_blocks, TPB>>>(ei, ea);

    embed_kernel<<<node_blocks, TPB>>>(x, atom, chir, hyb);

    for (int l = 0; l < 5; ++l) {
        eec_kernel<<<24, 32>>>(e1 + (size_t)l * 6 * D, e2 + (size_t)l * 4 * D);
        // gather-aggregate; for l>0 apply previous layer's BN+ReLU on the fly
        agg_kernel<<<node_blocks, TPB>>>((l == 0) ? p_h : p_h2, (l > 0) ? 1 : 0);
        // Linear1 + ReLU
        gemm_tf32x3_kernel<<<dim3(2, mrows), 256, smbytes>>>(
            p_agg, W1 + (size_t)l * D * 2 * D, b1 + (size_t)l * 2 * D, p_mid,
            NN, 2 * D, D, 1, 0);
        zero_stats_kernel<<<1, 128>>>();
        // Linear2 with fused column stats
        gemm_tf32x3_kernel<<<dim3(1, mrows), 256, smbytes>>>(
            p_mid, W2 + (size_t)l * 2 * D * D, b2 + (size_t)l * D, p_h2,
            NN, D, 2 * D, 0, 1);
        bnprep_kernel<<<1, 128>>>(gamma + (size_t)l * D, beta + (size_t)l * D);
        if (l == 4)
            bn_final_kernel<<<node_blocks, TPB>>>(p_h2, out);
    }
}

// round 6
// speedup vs baseline: 1.1016x; 1.1016x over previous
#include <cuda_runtime.h>
#include <cuda_bf16.h>
#include <cstdint>
#include <cstddef>

#define NN 50000
#define NE 600000
#define D 128
#define BN_EPS 1e-5f

// ---------------- scratch (device globals) -------------------------------------
__device__ float g_h[NN * D];        // node features between layers (post-BN)
__device__ float g_agg[NN * D];
__device__ float g_mid[NN * 2 * D];
__device__ float g_h2[NN * D];       // pre-BN output of each layer
__device__ float g_sum[D];
__device__ float g_sumsq[D];
__device__ float g_bns[D];           // BN scale per column
__device__ float g_bnt[D];           // BN shift per column
// CSR structures
__device__ int   g_cnt[NN];
__device__ int   g_rowstart[NN + 1];
__device__ int   g_cursor[NN];
__device__ int   g_edges[NE];        // src | (combo << 16)
__device__ float g_eec[24 * D];

// ---------------- input embedding ---------------------------------------------
__global__ void embed_kernel(const int* __restrict__ x,
                             const float* __restrict__ atom,
                             const float* __restrict__ chir,
                             const float* __restrict__ hyb) {
    int t = blockIdx.x * blockDim.x + threadIdx.x;
    int node = t >> 5, lane = t & 31;
    if (node >= NN) return;
    int x0 = x[node * 3 + 0];
    int x1 = x[node * 3 + 1];
    int x2 = x[node * 3 + 2];
    float4 a = ((const float4*)(atom + (size_t)x0 * D))[lane];
    float4 c = ((const float4*)(chir + (size_t)x1 * D))[lane];
    float4 y = ((const float4*)(hyb  + (size_t)x2 * D))[lane];
    ((float4*)g_h)[(size_t)node * 32 + lane] =
        make_float4(a.x + c.x + y.x, a.y + c.y + y.y,
                    a.z + c.z + y.z, a.w + c.w + y.w);
}

// ---------------- CSR build ----------------------------------------------------
__global__ void count_kernel(const int* __restrict__ ei) {
    int e = blockIdx.x * blockDim.x + threadIdx.x;
    if (e >= NE) return;
    atomicAdd(&g_cnt[ei[NE + e]], 1);
}

__global__ void scan_kernel() {
    __shared__ int warpsum[32];
    __shared__ int carry;
    int lane = threadIdx.x & 31, wid = threadIdx.x >> 5;
    if (threadIdx.x == 0) carry = 0;
    __syncthreads();
    for (int base = 0; base < NN; base += 1024) {
        int i = base + threadIdx.x;
        int v = (i < NN) ? g_cnt[i] : 0;
        int xs = v;
#pragma unroll
        for (int off = 1; off < 32; off <<= 1) {
            int t = __shfl_up_sync(0xffffffff, xs, off);
            if (lane >= off) xs += t;
        }
        if (lane == 31) warpsum[wid] = xs;
        __syncthreads();
        if (wid == 0) {
            int w = warpsum[lane];
#pragma unroll
            for (int off = 1; off < 32; off <<= 1) {
                int t = __shfl_up_sync(0xffffffff, w, off);
                if (lane >= off) w += t;
            }
            warpsum[lane] = w;
        }
        __syncthreads();
        int wpre = (wid > 0) ? warpsum[wid - 1] : 0;
        int incl = xs + wpre;
        int excl = incl - v + carry;
        if (i < NN) { g_rowstart[i] = excl; g_cursor[i] = excl; }
        __syncthreads();
        if (threadIdx.x == 1023) carry += incl;
        __syncthreads();
    }
    if (threadIdx.x == 0) g_rowstart[NN] = carry;
}

__global__ void fill_kernel(const int* __restrict__ ei,
                            const int* __restrict__ ea) {
    int e = blockIdx.x * blockDim.x + threadIdx.x;
    if (e >= NE) return;
    int dst = ei[NE + e];
    int pos = atomicAdd(&g_cursor[dst], 1);
    int cb = ea[2 * e] * 4 + ea[2 * e + 1];
    g_edges[pos] = ei[e] | (cb << 16);
}

// ---------------- per-layer edge-combo table ------------------------------------
__global__ void eec_kernel(const float* __restrict__ e1l,
                           const float* __restrict__ e2l) {
    int cb = blockIdx.x;
    int lane = threadIdx.x;
    int a0 = cb >> 2, a1 = cb & 3;
    float4 v1 = ((const float4*)(e1l + (size_t)a0 * D))[lane];
    float4 v2 = ((const float4*)(e2l + (size_t)a1 * D))[lane];
    ((float4*)g_eec)[cb * 32 + lane] =
        make_float4(v1.x + v2.x, v1.y + v2.y, v1.z + v2.z, v1.w + v2.w);
}

// ---------------- gather-aggregate: one warp per dst node, 4-edge unroll --------
__global__ void agg_kernel(const float* __restrict__ h) {
    int t = blockIdx.x * blockDim.x + threadIdx.x;
    int n = t >> 5, lane = t & 31;
    if (n >= NN) return;
    int beg = g_rowstart[n], end = g_rowstart[n + 1];
    float4 acc = make_float4(0.f, 0.f, 0.f, 0.f);
    int i = beg;
    for (; i + 3 < end; i += 4) {
        int p0 = g_edges[i];
        int p1 = g_edges[i + 1];
        int p2 = g_edges[i + 2];
        int p3 = g_edges[i + 3];
        float4 a0 = ((const float4*)h)[(size_t)(p0 & 0xFFFF) * 32 + lane];
        float4 a1 = ((const float4*)h)[(size_t)(p1 & 0xFFFF) * 32 + lane];
        float4 a2 = ((const float4*)h)[(size_t)(p2 & 0xFFFF) * 32 + lane];
        float4 a3 = ((const float4*)h)[(size_t)(p3 & 0xFFFF) * 32 + lane];
        float4 e0 = ((const float4*)g_eec)[(p0 >> 16) * 32 + lane];
        float4 e1v = ((const float4*)g_eec)[(p1 >> 16) * 32 + lane];
        float4 e2v = ((const float4*)g_eec)[(p2 >> 16) * 32 + lane];
        float4 e3v = ((const float4*)g_eec)[(p3 >> 16) * 32 + lane];
        acc.x += (a0.x + e0.x) + (a1.x + e1v.x) + (a2.x + e2v.x) + (a3.x + e3v.x);
        acc.y += (a0.y + e0.y) + (a1.y + e1v.y) + (a2.y + e2v.y) + (a3.y + e3v.y);
        acc.z += (a0.z + e0.z) + (a1.z + e1v.z) + (a2.z + e2v.z) + (a3.z + e3v.z);
        acc.w += (a0.w + e0.w) + (a1.w + e1v.w) + (a2.w + e2v.w) + (a3.w + e3v.w);
    }
    for (; i < end; ++i) {
        int p0 = g_edges[i];
        float4 a = ((const float4*)h)[(size_t)(p0 & 0xFFFF) * 32 + lane];
        float4 e0 = ((const float4*)g_eec)[(p0 >> 16) * 32 + lane];
        acc.x += a.x + e0.x;
        acc.y += a.y + e0.y;
        acc.z += a.z + e0.z;
        acc.w += a.w + e0.w;
    }
    ((float4*)g_agg)[(size_t)n * 32 + lane] = acc;
}

// ---------------- BN scale/shift prep -------------------------------------------
__global__ void bnprep_kernel(const float* __restrict__ gamma,
                              const float* __restrict__ beta) {
    int c = threadIdx.x;
    const float inv = 1.0f / (float)NN;
    float mean = g_sum[c] * inv;
    float var = g_sumsq[c] * inv - mean * mean;
    float s = gamma[c] * rsqrtf(var + BN_EPS);
    g_bns[c] = s;
    g_bnt[c] = beta[c] - mean * s;
}

// ---------------- BN apply (once per node) ---------------------------------------
__global__ void bn_apply_kernel(const float* __restrict__ h2,
                                float* __restrict__ outp, int relu) {
    int t = blockIdx.x * blockDim.x + threadIdx.x;
    int node = t >> 5, lane = t & 31;
    if (node >= NN) return;
    float4 s4 = ((const float4*)g_bns)[lane];
    float4 t4 = ((const float4*)g_bnt)[lane];
    float4 v = ((const float4*)h2)[(size_t)node * 32 + lane];
    float4 o = make_float4(fmaf(s4.x, v.x, t4.x), fmaf(s4.y, v.y, t4.y),
                           fmaf(s4.z, v.z, t4.z), fmaf(s4.w, v.w, t4.w));
    if (relu) {
        o.x = fmaxf(o.x, 0.f); o.y = fmaxf(o.y, 0.f);
        o.z = fmaxf(o.z, 0.f); o.w = fmaxf(o.w, 0.f);
    }
    ((float4*)outp)[(size_t)node * 32 + lane] = o;
}

__global__ void zero_stats_kernel() {
    g_sum[threadIdx.x] = 0.f;
    g_sumsq[threadIdx.x] = 0.f;
}

// ---------------- 3xTF32 GEMM with staged hi/lo split + optional fused stats ----
__device__ __forceinline__ uint32_t tf32_rna_u(float x) {
    uint32_t u;
    asm("cvt.rna.tf32.f32 %0, %1;" : "=r"(u) : "f"(x));
    return u;
}

#define MMA_TF32(acc, a, b)                                              \
    asm volatile(                                                        \
        "mma.sync.aligned.m16n8k8.row.col.f32.tf32.tf32.f32 "            \
        "{%0,%1,%2,%3}, {%4,%5,%6,%7}, {%8,%9}, {%0,%1,%2,%3};\n"        \
        : "+f"(acc[0]), "+f"(acc[1]), "+f"(acc[2]), "+f"(acc[3])         \
        : "r"(a[0]), "r"(a[1]), "r"(a[2]), "r"(a[3]),                    \
          "r"(b[0]), "r"(b[1]))

#define SM_ASZ (128 * 36)
#define SM_BSZ (32 * 132)
#define SMEM_FLOATS (2 * SM_ASZ + 2 * SM_BSZ)

__device__ __forceinline__ void split_store(float4 v, float* hi, float* lo) {
    uint32_t hx = tf32_rna_u(v.x), hy = tf32_rna_u(v.y),
             hz = tf32_rna_u(v.z), hw = tf32_rna_u(v.w);
    uint32_t lx = tf32_rna_u(v.x - __uint_as_float(hx));
    uint32_t ly = tf32_rna_u(v.y - __uint_as_float(hy));
    uint32_t lz = tf32_rna_u(v.z - __uint_as_float(hz));
    uint32_t lw = tf32_rna_u(v.w - __uint_as_float(hw));
    *(float4*)hi = make_float4(__uint_as_float(hx), __uint_as_float(hy),
                               __uint_as_float(hz), __uint_as_float(hw));
    *(float4*)lo = make_float4(__uint_as_float(lx), __uint_as_float(ly),
                               __uint_as_float(lz), __uint_as_float(lw));
}

__global__ __launch_bounds__(256) void gemm_tf32x3_kernel(
    const float* __restrict__ A, const float* __restrict__ B,
    const float* __restrict__ bias, float* __restrict__ C,
    int M, int N, int K, int relu, int do_stats) {
    extern __shared__ float sm[];
    float* As_hi = sm;
    float* As_lo = sm + SM_ASZ;
    float* Bs_hi = sm + 2 * SM_ASZ;
    float* Bs_lo = sm + 2 * SM_ASZ + SM_BSZ;

    const int tid  = threadIdx.x;
    const int warp = tid >> 5, lane = tid & 31;
    const int gid  = lane >> 2;
    const int tig  = lane & 3;
    const int wm   = (warp & 3) * 32;
    const int wn   = (warp >> 2) * 64;
    const int m0   = blockIdx.y * 128;
    const int n0b  = blockIdx.x * 128;

    float acc[2][8][4];
#pragma unroll
    for (int mi = 0; mi < 2; mi++)
#pragma unroll
        for (int ni = 0; ni < 8; ni++)
#pragma unroll
            for (int q = 0; q < 4; q++) acc[mi][ni][q] = 0.f;

    const int ar = tid >> 3, ac = (tid & 7) << 2;
    const int br = tid >> 5, bc = (tid & 31) << 2;

    for (int k0 = 0; k0 < K; k0 += 32) {
#pragma unroll
        for (int i = 0; i < 4; i++) {
            int r = ar + i * 32;
            float4 v = make_float4(0.f, 0.f, 0.f, 0.f);
            if (m0 + r < M)
                v = *(const float4*)(A + (size_t)(m0 + r) * K + k0 + ac);
            split_store(v, &As_hi[r * 36 + ac], &As_lo[r * 36 + ac]);
        }
#pragma unroll
        for (int i = 0; i < 4; i++) {
            int r = br + i * 8;
            float4 v = *(const float4*)(B + (size_t)(k0 + r) * N + n0b + bc);
            split_store(v, &Bs_hi[r * 132 + bc], &Bs_lo[r * 132 + bc]);
        }
        __syncthreads();

#pragma unroll
        for (int ks = 0; ks < 4; ks++) {
            const int kk = ks * 8;
            uint32_t ah[2][4], al[2][4], bh[8][2], bl[8][2];
#pragma unroll
            for (int mi = 0; mi < 2; mi++) {
                int r0 = wm + mi * 16 + gid;
                ah[mi][0] = __float_as_uint(As_hi[r0 * 36 + kk + tig]);
                ah[mi][1] = __float_as_uint(As_hi[(r0 + 8) * 36 + kk + tig]);
                ah[mi][2] = __float_as_uint(As_hi[r0 * 36 + kk + tig + 4]);
                ah[mi][3] = __float_as_uint(As_hi[(r0 + 8) * 36 + kk + tig + 4]);
                al[mi][0] = __float_as_uint(As_lo[r0 * 36 + kk + tig]);
                al[mi][1] = __float_as_uint(As_lo[(r0 + 8) * 36 + kk + tig]);
                al[mi][2] = __float_as_uint(As_lo[r0 * 36 + kk + tig + 4]);
                al[mi][3] = __float_as_uint(As_lo[(r0 + 8) * 36 + kk + tig + 4]);
            }
#pragma unroll
            for (int ni = 0; ni < 8; ni++) {
                int c0 = wn + ni * 8 + gid;
                bh[ni][0] = __float_as_uint(Bs_hi[(kk + tig) * 132 + c0]);
                bh[ni][1] = __float_as_uint(Bs_hi[(kk + tig + 4) * 132 + c0]);
                bl[ni][0] = __float_as_uint(Bs_lo[(kk + tig) * 132 + c0]);
                bl[ni][1] = __float_as_uint(Bs_lo[(kk + tig + 4) * 132 + c0]);
            }
#pragma unroll
            for (int mi = 0; mi < 2; mi++)
#pragma unroll
                for (int ni = 0; ni < 8; ni++) {
                    MMA_TF32(acc[mi][ni], al[mi], bh[ni]);
                    MMA_TF32(acc[mi][ni], ah[mi], bl[ni]);
                    MMA_TF32(acc[mi][ni], ah[mi], bh[ni]);
                }
        }
        __syncthreads();
    }

    // epilogue: bias (+relu) store, plus optional per-column stats
    float ls[16], ls2[16];
#pragma unroll
    for (int j = 0; j < 16; j++) { ls[j] = 0.f; ls2[j] = 0.f; }

#pragma unroll
    for (int mi = 0; mi < 2; mi++) {
        int r0 = m0 + wm + mi * 16 + gid;
#pragma unroll
        for (int ni = 0; ni < 8; ni++) {
            int gc = n0b + wn + ni * 8 + 2 * tig;
            float bv0 = bias[gc], bv1 = bias[gc + 1];
            float v0 = acc[mi][ni][0] + bv0;
            float v1 = acc[mi][ni][1] + bv1;
            float v2 = acc[mi][ni][2] + bv0;
            float v3 = acc[mi][ni][3] + bv1;
            if (relu) {
                v0 = fmaxf(v0, 0.f); v1 = fmaxf(v1, 0.f);
                v2 = fmaxf(v2, 0.f); v3 = fmaxf(v3, 0.f);
            }
            bool ok0 = (r0 < M), ok1 = (r0 + 8 < M);
            if (ok0)
                *(float2*)(C + (size_t)r0 * N + gc) = make_float2(v0, v1);
            if (ok1)
                *(float2*)(C + (size_t)(r0 + 8) * N + gc) = make_float2(v2, v3);
            if (do_stats) {
                if (ok0) {
                    ls[ni * 2]     += v0; ls2[ni * 2]     += v0 * v0;
                    ls[ni * 2 + 1] += v1; ls2[ni * 2 + 1] += v1 * v1;
                }
                if (ok1) {
                    ls[ni * 2]     += v2; ls2[ni * 2]     += v2 * v2;
                    ls[ni * 2 + 1] += v3; ls2[ni * 2 + 1] += v3 * v3;
                }
            }
        }
    }

    if (do_stats) {
#pragma unroll
        for (int j = 0; j < 16; j++) {
#pragma unroll
            for (int off = 4; off < 32; off <<= 1) {
                ls[j]  += __shfl_xor_sync(0xffffffff, ls[j], off);
                ls2[j] += __shfl_xor_sync(0xffffffff, ls2[j], off);
            }
        }
        float* cs  = sm;        // smem reusable after final __syncthreads
        float* cs2 = sm + 128;
        if (tid < 128) { cs[tid] = 0.f; cs2[tid] = 0.f; }
        __syncthreads();
        if (lane < 4) {
#pragma unroll
            for (int ni = 0; ni < 8; ni++) {
                int c0 = wn + ni * 8 + 2 * lane;
                atomicAdd(&cs[c0],      ls[ni * 2]);
                atomicAdd(&cs2[c0],     ls2[ni * 2]);
                atomicAdd(&cs[c0 + 1],  ls[ni * 2 + 1]);
                atomicAdd(&cs2[c0 + 1], ls2[ni * 2 + 1]);
            }
        }
        __syncthreads();
        if (tid < 128) {
            atomicAdd(&g_sum[tid],   cs[tid]);
            atomicAdd(&g_sumsq[tid], cs2[tid]);
        }
    }
}

// ---------------- launch --------------------------------------------------------
extern "C" void kernel_launch(void* const* d_in, const int* in_sizes, int n_in,
                              void* d_out, int out_size) {
    const int*   x     = (const int*)d_in[0];
    const int*   ei    = (const int*)d_in[1];
    const int*   ea    = (const int*)d_in[2];
    const float* atom  = (const float*)d_in[3];
    const float* chir  = (const float*)d_in[4];
    const float* hyb   = (const float*)d_in[5];
    const float* e1    = (const float*)d_in[6];
    const float* e2    = (const float*)d_in[7];
    const float* W1    = (const float*)d_in[8];
    const float* b1    = (const float*)d_in[9];
    const float* W2    = (const float*)d_in[10];
    const float* b2    = (const float*)d_in[11];
    const float* gamma = (const float*)d_in[12];
    const float* beta  = (const float*)d_in[13];
    float* out = (float*)d_out;

    float *p_h, *p_agg, *p_mid, *p_h2;
    int* p_cnt;
    cudaGetSymbolAddress((void**)&p_h,   g_h);
    cudaGetSymbolAddress((void**)&p_agg, g_agg);
    cudaGetSymbolAddress((void**)&p_mid, g_mid);
    cudaGetSymbolAddress((void**)&p_h2,  g_h2);
    cudaGetSymbolAddress((void**)&p_cnt, g_cnt);

    const size_t smbytes = SMEM_FLOATS * sizeof(float);
    cudaFuncSetAttribute(gemm_tf32x3_kernel,
                         cudaFuncAttributeMaxDynamicSharedMemorySize,
                         (int)smbytes);

    const int TPB = 256;
    const int node_blocks = (NN * 32 + TPB - 1) / TPB;
    const int edge_blocks = (NE + TPB - 1) / TPB;
    const int mrows = (NN + 127) / 128;

    // CSR build (layer-invariant)
    cudaMemsetAsync(p_cnt, 0, NN * sizeof(int));
    count_kernel<<<edge_blocks, TPB>>>(ei);
    scan_kernel<<<1, 1024>>>();
    fill_kernel<<<edge_blocks, TPB>>>(ei, ea);

    embed_kernel<<<node_blocks, TPB>>>(x, atom, chir, hyb);

    for (int l = 0; l < 5; ++l) {
        eec_kernel<<<24, 32>>>(e1 + (size_t)l * 6 * D, e2 + (size_t)l * 4 * D);
        agg_kernel<<<node_blocks, TPB>>>(p_h);
        // Linear1 + ReLU
        gemm_tf32x3_kernel<<<dim3(2, mrows), 256, smbytes>>>(
            p_agg, W1 + (size_t)l * D * 2 * D, b1 + (size_t)l * 2 * D, p_mid,
            NN, 2 * D, D, 1, 0);
        zero_stats_kernel<<<1, 128>>>();
        // Linear2 with fused column stats
        gemm_tf32x3_kernel<<<dim3(1, mrows), 256, smbytes>>>(
            p_mid, W2 + (size_t)l * 2 * D * D, b2 + (size_t)l * D, p_h2,
            NN, D, 2 * D, 0, 1);
        bnprep_kernel<<<1, 128>>>(gamma + (size_t)l * D, beta + (size_t)l * D);
        // BN apply once per node: hidden layers -> p_h with ReLU, last -> out
        bn_apply_kernel<<<node_blocks, TPB>>>(p_h2, (l == 4) ? out : p_h,
                                              (l < 4) ? 1 : 0);
    }
}

// round 7
// speedup vs baseline: 1.1972x; 1.0868x over previous
#include <cuda_runtime.h>
#include <cuda_bf16.h>
#include <cstdint>
#include <cstddef>

#define NN 50000
#define NE 600000
#define D 128
#define BN_EPS 1e-5f

// ---------------- scratch (device globals) -------------------------------------
__device__ float g_h[NN * D];                 // post-BN node features (fp32)
__device__ __nv_bfloat16 g_agg_hi[NN * D];    // aggregate, bf16 split
__device__ __nv_bfloat16 g_agg_lo[NN * D];
__device__ __nv_bfloat16 g_mid_hi[NN * 2 * D];
__device__ __nv_bfloat16 g_mid_lo[NN * 2 * D];
__device__ float g_h2[NN * D];                // pre-BN layer output (fp32)
__device__ float g_sum[D];
__device__ float g_sumsq[D];
__device__ float g_bns[D];
__device__ float g_bnt[D];
// pre-split transposed weights: wt1[l][n][k] (n<256,k<128), wt2[l][n][k] (n<128,k<256)
__device__ __nv_bfloat16 g_wt1_hi[5 * 256 * 128];
__device__ __nv_bfloat16 g_wt1_lo[5 * 256 * 128];
__device__ __nv_bfloat16 g_wt2_hi[5 * 128 * 256];
__device__ __nv_bfloat16 g_wt2_lo[5 * 128 * 256];
// CSR structures
__device__ int   g_cnt[NN];
__device__ int   g_rowstart[NN + 1];
__device__ int   g_cursor[NN];
__device__ int   g_edges[NE];                 // src | (combo << 16)
__device__ float g_eec[24 * D];

// ---------------- helpers -------------------------------------------------------
__device__ __forceinline__ uint32_t pack2bf(float x, float y) {
    __nv_bfloat162 h = __floats2bfloat162_rn(x, y);
    return *(uint32_t*)&h;
}
__device__ __forceinline__ void split2(float x, float y,
                                       uint32_t& hi, uint32_t& lo) {
    __nv_bfloat16 hx = __float2bfloat16(x);
    __nv_bfloat16 hy = __float2bfloat16(y);
    float rx = x - __bfloat162float(hx);
    float ry = y - __bfloat162float(hy);
    __nv_bfloat162 h2 = __halves2bfloat162(hx, hy);
    hi = *(uint32_t*)&h2;
    lo = pack2bf(rx, ry);
}

// ---------------- input embedding ---------------------------------------------
__global__ void embed_kernel(const int* __restrict__ x,
                             const float* __restrict__ atom,
                             const float* __restrict__ chir,
                             const float* __restrict__ hyb) {
    int t = blockIdx.x * blockDim.x + threadIdx.x;
    int node = t >> 5, lane = t & 31;
    if (node >= NN) return;
    int x0 = x[node * 3 + 0];
    int x1 = x[node * 3 + 1];
    int x2 = x[node * 3 + 2];
    float4 a = ((const float4*)(atom + (size_t)x0 * D))[lane];
    float4 c = ((const float4*)(chir + (size_t)x1 * D))[lane];
    float4 y = ((const float4*)(hyb  + (size_t)x2 * D))[lane];
    ((float4*)g_h)[(size_t)node * 32 + lane] =
        make_float4(a.x + c.x + y.x, a.y + c.y + y.y,
                    a.z + c.z + y.z, a.w + c.w + y.w);
}

// ---------------- weight prep: transpose + bf16 split --------------------------
// W1[l][k][n] (k<128,n<256) -> wt1[l][n][k]; W2[l][k][n] (k<256,n<128) -> wt2[l][n][k]
__global__ void wprep_kernel(const float* __restrict__ W1,
                             const float* __restrict__ W2) {
    int t = blockIdx.x * blockDim.x + threadIdx.x;
    int total = 5 * 128 * 256;       // per-weight element count
    if (t < total) {                 // W1
        int l = t / (128 * 256);
        int r = t % (128 * 256);
        int k = r / 256, n = r % 256;
        float v = W1[t];
        __nv_bfloat16 h = __float2bfloat16(v);
        g_wt1_hi[l * 32768 + n * 128 + k] = h;
        g_wt1_lo[l * 32768 + n * 128 + k] =
            __float2bfloat16(v - __bfloat162float(h));
    } else if (t < 2 * total) {      // W2
        int u = t - total;
        int l = u / (256 * 128);
        int r = u % (256 * 128);
        int k = r / 128, n = r % 128;
        float v = W2[u];
        __nv_bfloat16 h = __float2bfloat16(v);
        g_wt2_hi[l * 32768 + n * 256 + k] = h;
        g_wt2_lo[l * 32768 + n * 256 + k] =
            __float2bfloat16(v - __bfloat162float(h));
    }
}

// ---------------- CSR build ----------------------------------------------------
__global__ void count_kernel(const int* __restrict__ ei) {
    int e = blockIdx.x * blockDim.x + threadIdx.x;
    if (e >= NE) return;
    atomicAdd(&g_cnt[ei[NE + e]], 1);
}

__global__ void scan_kernel() {
    __shared__ int warpsum[32];
    __shared__ int carry;
    int lane = threadIdx.x & 31, wid = threadIdx.x >> 5;
    if (threadIdx.x == 0) carry = 0;
    __syncthreads();
    for (int base = 0; base < NN; base += 1024) {
        int i = base + threadIdx.x;
        int v = (i < NN) ? g_cnt[i] : 0;
        int xs = v;
#pragma unroll
        for (int off = 1; off < 32; off <<= 1) {
            int t = __shfl_up_sync(0xffffffff, xs, off);
            if (lane >= off) xs += t;
        }
        if (lane == 31) warpsum[wid] = xs;
        __syncthreads();
        if (wid == 0) {
            int w = warpsum[lane];
#pragma unroll
            for (int off = 1; off < 32; off <<= 1) {
                int t = __shfl_up_sync(0xffffffff, w, off);
                if (lane >= off) w += t;
            }
            warpsum[lane] = w;
        }
        __syncthreads();
        int wpre = (wid > 0) ? warpsum[wid - 1] : 0;
        int incl = xs + wpre;
        int excl = incl - v + carry;
        if (i < NN) { g_rowstart[i] = excl; g_cursor[i] = excl; }
        __syncthreads();
        if (threadIdx.x == 1023) carry += incl;
        __syncthreads();
    }
    if (threadIdx.x == 0) g_rowstart[NN] = carry;
}

__global__ void fill_kernel(const int* __restrict__ ei,
                            const int* __restrict__ ea) {
    int e = blockIdx.x * blockDim.x + threadIdx.x;
    if (e >= NE) return;
    int dst = ei[NE + e];
    int pos = atomicAdd(&g_cursor[dst], 1);
    int cb = ea[2 * e] * 4 + ea[2 * e + 1];
    g_edges[pos] = ei[e] | (cb << 16);
}

// ---------------- per-layer edge-combo table ------------------------------------
__global__ void eec_kernel(const float* __restrict__ e1l,
                           const float* __restrict__ e2l) {
    int cb = blockIdx.x;
    int lane = threadIdx.x;
    int a0 = cb >> 2, a1 = cb & 3;
    float4 v1 = ((const float4*)(e1l + (size_t)a0 * D))[lane];
    float4 v2 = ((const float4*)(e2l + (size_t)a1 * D))[lane];
    ((float4*)g_eec)[cb * 32 + lane] =
        make_float4(v1.x + v2.x, v1.y + v2.y, v1.z + v2.z, v1.w + v2.w);
}

// ---------------- gather-aggregate: warp per node, emits bf16 hi/lo -------------
__global__ void agg_kernel(const float* __restrict__ h) {
    int t = blockIdx.x * blockDim.x + threadIdx.x;
    int n = t >> 5, lane = t & 31;
    if (n >= NN) return;
    int beg = g_rowstart[n], end = g_rowstart[n + 1];
    float4 acc = make_float4(0.f, 0.f, 0.f, 0.f);
    int i = beg;
    for (; i + 3 < end; i += 4) {
        int p0 = g_edges[i];
        int p1 = g_edges[i + 1];
        int p2 = g_edges[i + 2];
        int p3 = g_edges[i + 3];
        float4 a0 = ((const float4*)h)[(size_t)(p0 & 0xFFFF) * 32 + lane];
        float4 a1 = ((const float4*)h)[(size_t)(p1 & 0xFFFF) * 32 + lane];
        float4 a2 = ((const float4*)h)[(size_t)(p2 & 0xFFFF) * 32 + lane];
        float4 a3 = ((const float4*)h)[(size_t)(p3 & 0xFFFF) * 32 + lane];
        float4 e0 = ((const float4*)g_eec)[(p0 >> 16) * 32 + lane];
        float4 e1v = ((const float4*)g_eec)[(p1 >> 16) * 32 + lane];
        float4 e2v = ((const float4*)g_eec)[(p2 >> 16) * 32 + lane];
        float4 e3v = ((const float4*)g_eec)[(p3 >> 16) * 32 + lane];
        acc.x += (a0.x + e0.x) + (a1.x + e1v.x) + (a2.x + e2v.x) + (a3.x + e3v.x);
        acc.y += (a0.y + e0.y) + (a1.y + e1v.y) + (a2.y + e2v.y) + (a3.y + e3v.y);
        acc.z += (a0.z + e0.z) + (a1.z + e1v.z) + (a2.z + e2v.z) + (a3.z + e3v.z);
        acc.w += (a0.w + e0.w) + (a1.w + e1v.w) + (a2.w + e2v.w) + (a3.w + e3v.w);
    }
    for (; i < end; ++i) {
        int p0 = g_edges[i];
        float4 a = ((const float4*)h)[(size_t)(p0 & 0xFFFF) * 32 + lane];
        float4 e0 = ((const float4*)g_eec)[(p0 >> 16) * 32 + lane];
        acc.x += a.x + e0.x;
        acc.y += a.y + e0.y;
        acc.z += a.z + e0.z;
        acc.w += a.w + e0.w;
    }
    uint32_t h0, l0, h1, l1;
    split2(acc.x, acc.y, h0, l0);
    split2(acc.z, acc.w, h1, l1);
    uint2* ph = (uint2*)g_agg_hi;
    uint2* pl = (uint2*)g_agg_lo;
    ph[(size_t)n * 32 + lane] = make_uint2(h0, h1);
    pl[(size_t)n * 32 + lane] = make_uint2(l0, l1);
}

// ---------------- BN ------------------------------------------------------------
__global__ void bnprep_kernel(const float* __restrict__ gamma,
                              const float* __restrict__ beta) {
    int c = threadIdx.x;
    const float inv = 1.0f / (float)NN;
    float mean = g_sum[c] * inv;
    float var = g_sumsq[c] * inv - mean * mean;
    float s = gamma[c] * rsqrtf(var + BN_EPS);
    g_bns[c] = s;
    g_bnt[c] = beta[c] - mean * s;
}

__global__ void bn_apply_kernel(const float* __restrict__ h2,
                                float* __restrict__ outp, int relu) {
    int t = blockIdx.x * blockDim.x + threadIdx.x;
    int node = t >> 5, lane = t & 31;
    if (node >= NN) return;
    float4 s4 = ((const float4*)g_bns)[lane];
    float4 t4 = ((const float4*)g_bnt)[lane];
    float4 v = ((const float4*)h2)[(size_t)node * 32 + lane];
    float4 o = make_float4(fmaf(s4.x, v.x, t4.x), fmaf(s4.y, v.y, t4.y),
                           fmaf(s4.z, v.z, t4.z), fmaf(s4.w, v.w, t4.w));
    if (relu) {
        o.x = fmaxf(o.x, 0.f); o.y = fmaxf(o.y, 0.f);
        o.z = fmaxf(o.z, 0.f); o.w = fmaxf(o.w, 0.f);
    }
    ((float4*)outp)[(size_t)node * 32 + lane] = o;
}

__global__ void zero_stats_kernel() {
    g_sum[threadIdx.x] = 0.f;
    g_sumsq[threadIdx.x] = 0.f;
}

// ---------------- bf16x3 tensor-core GEMM ---------------------------------------
// BM=BN=128, BK=32, 256 threads (8 warps 4x2), m16n8k16 mma, pre-split operands.
// A: [M][K] bf16 hi/lo, B: [N][K] bf16 hi/lo (both k-contiguous).
#define MMA_BF16(acc, a, b)                                              \
    asm volatile(                                                        \
        "mma.sync.aligned.m16n8k16.row.col.f32.bf16.bf16.f32 "           \
        "{%0,%1,%2,%3}, {%4,%5,%6,%7}, {%8,%9}, {%0,%1,%2,%3};\n"        \
        : "+f"(acc[0]), "+f"(acc[1]), "+f"(acc[2]), "+f"(acc[3])         \
        : "r"(a[0]), "r"(a[1]), "r"(a[2]), "r"(a[3]),                    \
          "r"(b[0]), "r"(b[1]))

#define PAD 40   // bf16 units per smem row (80B stride: uint4-aligned, LDS conflict-free)

__global__ __launch_bounds__(256) void gemm_bf16x3_kernel(
    const __nv_bfloat16* __restrict__ Ah, const __nv_bfloat16* __restrict__ Al,
    const __nv_bfloat16* __restrict__ Bh, const __nv_bfloat16* __restrict__ Bl,
    const float* __restrict__ bias,
    float* __restrict__ Cf, __nv_bfloat16* __restrict__ Ch,
    __nv_bfloat16* __restrict__ Cl,
    int M, int N, int K, int relu, int do_stats, int out_bf16) {
    __shared__ __align__(16) __nv_bfloat16 As_hi[128 * PAD];
    __shared__ __align__(16) __nv_bfloat16 As_lo[128 * PAD];
    __shared__ __align__(16) __nv_bfloat16 Bs_hi[128 * PAD];
    __shared__ __align__(16) __nv_bfloat16 Bs_lo[128 * PAD];

    const int tid  = threadIdx.x;
    const int warp = tid >> 5, lane = tid & 31;
    const int gid  = lane >> 2;
    const int tig  = lane & 3;
    const int wm   = (warp & 3) * 32;
    const int wn   = (warp >> 2) * 64;
    const int m0   = blockIdx.y * 128;
    const int n0b  = blockIdx.x * 128;

    float acc[2][8][4];
#pragma unroll
    for (int mi = 0; mi < 2; mi++)
#pragma unroll
        for (int ni = 0; ni < 8; ni++)
#pragma unroll
            for (int q = 0; q < 4; q++) acc[mi][ni][q] = 0.f;

    const int sr = tid >> 2;            // 0..63
    const int sc = (tid & 3) * 8;       // k offset (bf16 units), uint4 = 8 bf16

    for (int k0 = 0; k0 < K; k0 += 32) {
        // stage A (128 x 32 bf16) hi+lo
#pragma unroll
        for (int i = 0; i < 2; i++) {
            int r = sr + i * 64;
            uint4 vh = make_uint4(0, 0, 0, 0), vl = make_uint4(0, 0, 0, 0);
            if (m0 + r < M) {
                vh = *(const uint4*)(Ah + (size_t)(m0 + r) * K + k0 + sc);
                vl = *(const uint4*)(Al + (size_t)(m0 + r) * K + k0 + sc);
            }
            *(uint4*)&As_hi[r * PAD + sc] = vh;
            *(uint4*)&As_lo[r * PAD + sc] = vl;
        }
        // stage B (128 x 32 bf16) hi+lo
#pragma unroll
        for (int i = 0; i < 2; i++) {
            int r = sr + i * 64;
            *(uint4*)&Bs_hi[r * PAD + sc] =
                *(const uint4*)(Bh + (size_t)(n0b + r) * K + k0 + sc);
            *(uint4*)&Bs_lo[r * PAD + sc] =
                *(const uint4*)(Bl + (size_t)(n0b + r) * K + k0 + sc);
        }
        __syncthreads();

#pragma unroll
        for (int ks = 0; ks < 2; ks++) {
            const int kk = ks * 16;
            uint32_t ah[2][4], al[2][4], bh[8][2], bl[8][2];
#pragma unroll
            for (int mi = 0; mi < 2; mi++) {
                int r0 = wm + mi * 16 + gid;
                ah[mi][0] = *(uint32_t*)&As_hi[r0 * PAD + kk + tig * 2];
                ah[mi][1] = *(uint32_t*)&As_hi[(r0 + 8) * PAD + kk + tig * 2];
                ah[mi][2] = *(uint32_t*)&As_hi[r0 * PAD + kk + 8 + tig * 2];
                ah[mi][3] = *(uint32_t*)&As_hi[(r0 + 8) * PAD + kk + 8 + tig * 2];
                al[mi][0] = *(uint32_t*)&As_lo[r0 * PAD + kk + tig * 2];
                al[mi][1] = *(uint32_t*)&As_lo[(r0 + 8) * PAD + kk + tig * 2];
                al[mi][2] = *(uint32_t*)&As_lo[r0 * PAD + kk + 8 + tig * 2];
                al[mi][3] = *(uint32_t*)&As_lo[(r0 + 8) * PAD + kk + 8 + tig * 2];
            }
#pragma unroll
            for (int ni = 0; ni < 8; ni++) {
                int c0 = wn + ni * 8 + gid;
                bh[ni][0] = *(uint32_t*)&Bs_hi[c0 * PAD + kk + tig * 2];
                bh[ni][1] = *(uint32_t*)&Bs_hi[c0 * PAD + kk + 8 + tig * 2];
                bl[ni][0] = *(uint32_t*)&Bs_lo[c0 * PAD + kk + tig * 2];
                bl[ni][1] = *(uint32_t*)&Bs_lo[c0 * PAD + kk + 8 + tig * 2];
            }
#pragma unroll
            for (int mi = 0; mi < 2; mi++)
#pragma unroll
                for (int ni = 0; ni < 8; ni++) {
                    MMA_BF16(acc[mi][ni], al[mi], bh[ni]);  // lo*hi
                    MMA_BF16(acc[mi][ni], ah[mi], bl[ni]);  // hi*lo
                    MMA_BF16(acc[mi][ni], ah[mi], bh[ni]);  // hi*hi
                }
        }
        __syncthreads();
    }

    // epilogue
    float ls[16], ls2[16];
#pragma unroll
    for (int j = 0; j < 16; j++) { ls[j] = 0.f; ls2[j] = 0.f; }

#pragma unroll
    for (int mi = 0; mi < 2; mi++) {
        int r0 = m0 + wm + mi * 16 + gid;
#pragma unroll
        for (int ni = 0; ni < 8; ni++) {
            int gc = n0b + wn + ni * 8 + 2 * tig;
            float bv0 = bias[gc], bv1 = bias[gc + 1];
            float v0 = acc[mi][ni][0] + bv0;
            float v1 = acc[mi][ni][1] + bv1;
            float v2 = acc[mi][ni][2] + bv0;
            float v3 = acc[mi][ni][3] + bv1;
            if (relu) {
                v0 = fmaxf(v0, 0.f); v1 = fmaxf(v1, 0.f);
                v2 = fmaxf(v2, 0.f); v3 = fmaxf(v3, 0.f);
            }
            bool ok0 = (r0 < M), ok1 = (r0 + 8 < M);
            if (out_bf16) {
                uint32_t h0, l0, h1, l1;
                split2(v0, v1, h0, l0);
                split2(v2, v3, h1, l1);
                if (ok0) {
                    *(uint32_t*)(Ch + (size_t)r0 * N + gc) = h0;
                    *(uint32_t*)(Cl + (size_t)r0 * N + gc) = l0;
                }
                if (ok1) {
                    *(uint32_t*)(Ch + (size_t)(r0 + 8) * N + gc) = h1;
                    *(uint32_t*)(Cl + (size_t)(r0 + 8) * N + gc) = l1;
                }
            } else {
                if (ok0)
                    *(float2*)(Cf + (size_t)r0 * N + gc) = make_float2(v0, v1);
                if (ok1)
                    *(float2*)(Cf + (size_t)(r0 + 8) * N + gc) = make_float2(v2, v3);
            }
            if (do_stats) {
                if (ok0) {
                    ls[ni * 2]     += v0; ls2[ni * 2]     += v0 * v0;
                    ls[ni * 2 + 1] += v1; ls2[ni * 2 + 1] += v1 * v1;
                }
                if (ok1) {
                    ls[ni * 2]     += v2; ls2[ni * 2]     += v2 * v2;
                    ls[ni * 2 + 1] += v3; ls2[ni * 2 + 1] += v3 * v3;
                }
            }
        }
    }

    if (do_stats) {
#pragma unroll
        for (int j = 0; j < 16; j++) {
#pragma unroll
            for (int off = 4; off < 32; off <<= 1) {
                ls[j]  += __shfl_xor_sync(0xffffffff, ls[j], off);
                ls2[j] += __shfl_xor_sync(0xffffffff, ls2[j], off);
            }
        }
        float* cs  = (float*)As_hi;   // smem reuse (after final sync)
        float* cs2 = (float*)As_lo;
        if (tid < 128) { cs[tid] = 0.f; cs2[tid] = 0.f; }
        __syncthreads();
        if (lane < 4) {
#pragma unroll
            for (int ni = 0; ni < 8; ni++) {
                int c0 = wn + ni * 8 + 2 * lane;
                atomicAdd(&cs[c0],      ls[ni * 2]);
                atomicAdd(&cs2[c0],     ls2[ni * 2]);
                atomicAdd(&cs[c0 + 1],  ls[ni * 2 + 1]);
                atomicAdd(&cs2[c0 + 1], ls2[ni * 2 + 1]);
            }
        }
        __syncthreads();
        if (tid < 128) {
            atomicAdd(&g_sum[tid],   cs[tid]);
            atomicAdd(&g_sumsq[tid], cs2[tid]);
        }
    }
}

// ---------------- launch --------------------------------------------------------
extern "C" void kernel_launch(void* const* d_in, const int* in_sizes, int n_in,
                              void* d_out, int out_size) {
    const int*   x     = (const int*)d_in[0];
    const int*   ei    = (const int*)d_in[1];
    const int*   ea    = (const int*)d_in[2];
    const float* atom  = (const float*)d_in[3];
    const float* chir  = (const float*)d_in[4];
    const float* hyb   = (const float*)d_in[5];
    const float* e1    = (const float*)d_in[6];
    const float* e2    = (const float*)d_in[7];
    const float* W1    = (const float*)d_in[8];
    const float* b1    = (const float*)d_in[9];
    const float* W2    = (const float*)d_in[10];
    const float* b2    = (const float*)d_in[11];
    const float* gamma = (const float*)d_in[12];
    const float* beta  = (const float*)d_in[13];
    float* out = (float*)d_out;

    float *p_h, *p_h2;
    int* p_cnt;
    __nv_bfloat16 *p_agg_hi, *p_agg_lo, *p_mid_hi, *p_mid_lo;
    __nv_bfloat16 *p_wt1_hi, *p_wt1_lo, *p_wt2_hi, *p_wt2_lo;
    cudaGetSymbolAddress((void**)&p_h,      g_h);
    cudaGetSymbolAddress((void**)&p_h2,     g_h2);
    cudaGetSymbolAddress((void**)&p_cnt,    g_cnt);
    cudaGetSymbolAddress((void**)&p_agg_hi, g_agg_hi);
    cudaGetSymbolAddress((void**)&p_agg_lo, g_agg_lo);
    cudaGetSymbolAddress((void**)&p_mid_hi, g_mid_hi);
    cudaGetSymbolAddress((void**)&p_mid_lo, g_mid_lo);
    cudaGetSymbolAddress((void**)&p_wt1_hi, g_wt1_hi);
    cudaGetSymbolAddress((void**)&p_wt1_lo, g_wt1_lo);
    cudaGetSymbolAddress((void**)&p_wt2_hi, g_wt2_hi);
    cudaGetSymbolAddress((void**)&p_wt2_lo, g_wt2_lo);

    const int TPB = 256;
    const int node_blocks = (NN * 32 + TPB - 1) / TPB;
    const int edge_blocks = (NE + TPB - 1) / TPB;
    const int mrows = (NN + 127) / 128;

    // CSR build + weight prep (layer-invariant)
    cudaMemsetAsync(p_cnt, 0, NN * sizeof(int));
    count_kernel<<<edge_blocks, TPB>>>(ei);
    scan_kernel<<<1, 1024>>>();
    fill_kernel<<<edge_blocks, TPB>>>(ei, ea);
    wprep_kernel<<<(2 * 5 * 128 * 256 + TPB - 1) / TPB, TPB>>>(W1, W2);

    embed_kernel<<<node_blocks, TPB>>>(x, atom, chir, hyb);

    for (int l = 0; l < 5; ++l) {
        eec_kernel<<<24, 32>>>(e1 + (size_t)l * 6 * D, e2 + (size_t)l * 4 * D);
        agg_kernel<<<node_blocks, TPB>>>(p_h);
        // Linear1 + ReLU -> mid (bf16 hi/lo)
        gemm_bf16x3_kernel<<<dim3(2, mrows), 256>>>(
            p_agg_hi, p_agg_lo,
            p_wt1_hi + (size_t)l * 32768, p_wt1_lo + (size_t)l * 32768,
            b1 + (size_t)l * 2 * D,
            nullptr, p_mid_hi, p_mid_lo,
            NN, 2 * D, D, 1, 0, 1);
        zero_stats_kernel<<<1, 128>>>();
        // Linear2 -> h2 (fp32) with fused column stats
        gemm_bf16x3_kernel<<<dim3(1, mrows), 256>>>(
            p_mid_hi, p_mid_lo,
            p_wt2_hi + (size_t)l * 32768, p_wt2_lo + (size_t)l * 32768,
            b2 + (size_t)l * D,
            p_h2, nullptr, nullptr,
            NN, D, 2 * D, 0, 1, 0);
        bnprep_kernel<<<1, 128>>>(gamma + (size_t)l * D, beta + (size_t)l * D);
        bn_apply_kernel<<<node_blocks, TPB>>>(p_h2, (l == 4) ? out : p_h,
                                              (l < 4) ? 1 : 0);
    }
}

// round 9
// speedup vs baseline: 1.4824x; 1.2382x over previous
#include <cuda_runtime.h>
#include <cuda_bf16.h>
#include <cstdint>
#include <cstddef>

#define NN 50000
#define NE 600000
#define D 128
#define BN_EPS 1e-5f

// ---------------- scratch (device globals) -------------------------------------
__device__ float g_h[NN * D];                 // post-BN node features (fp32)
__device__ __nv_bfloat16 g_agg_hi[NN * D];    // aggregate, bf16 split
__device__ __nv_bfloat16 g_agg_lo[NN * D];
__device__ __nv_bfloat16 g_mid_hi[NN * 2 * D];
__device__ __nv_bfloat16 g_mid_lo[NN * 2 * D];
__device__ float g_h2[NN * D];                // pre-BN layer output (fp32)
__device__ float g_sum[D];
__device__ float g_sumsq[D];
__device__ float g_bns[D];
__device__ float g_bnt[D];
// pre-split transposed weights
__device__ __nv_bfloat16 g_wt1_hi[5 * 256 * 128];
__device__ __nv_bfloat16 g_wt1_lo[5 * 256 * 128];
__device__ __nv_bfloat16 g_wt2_hi[5 * 128 * 256];
__device__ __nv_bfloat16 g_wt2_lo[5 * 128 * 256];
// CSR structures
__device__ int   g_cnt[NN];
__device__ int   g_rowstart[NN + 1];
__device__ int   g_cursor[NN];
__device__ int   g_edges[NE];                 // src | (combo << 16)
__device__ float g_eec[5 * 24 * D];           // all layers precomputed

// ---------------- helpers -------------------------------------------------------
__device__ __forceinline__ uint32_t pack2bf(float x, float y) {
    __nv_bfloat162 h = __floats2bfloat162_rn(x, y);
    return *(uint32_t*)&h;
}
__device__ __forceinline__ void split2(float x, float y,
                                       uint32_t& hi, uint32_t& lo) {
    __nv_bfloat16 hx = __float2bfloat16(x);
    __nv_bfloat16 hy = __float2bfloat16(y);
    float rx = x - __bfloat162float(hx);
    float ry = y - __bfloat162float(hy);
    __nv_bfloat162 h2 = __halves2bfloat162(hx, hy);
    hi = *(uint32_t*)&h2;
    lo = pack2bf(rx, ry);
}
__device__ __forceinline__ void cp_async16(void* dst, const void* src,
                                           int src_bytes) {
    uint32_t d = (uint32_t)__cvta_generic_to_shared(dst);
    asm volatile("cp.async.cg.shared.global [%0], [%1], 16, %2;\n"
                 :: "r"(d), "l"(src), "r"(src_bytes));
}
#define CP_COMMIT() asm volatile("cp.async.commit_group;\n" ::: "memory")
#define CP_WAIT(n)  asm volatile("cp.async.wait_group %0;\n" :: "n"(n) : "memory")

// ---------------- input embedding ---------------------------------------------
__global__ void embed_kernel(const int* __restrict__ x,
                             const float* __restrict__ atom,
                             const float* __restrict__ chir,
                             const float* __restrict__ hyb) {
    int t = blockIdx.x * blockDim.x + threadIdx.x;
    int node = t >> 5, lane = t & 31;
    if (node >= NN) return;
    int x0 = x[node * 3 + 0];
    int x1 = x[node * 3 + 1];
    int x2 = x[node * 3 + 2];
    float4 a = ((const float4*)(atom + (size_t)x0 * D))[lane];
    float4 c = ((const float4*)(chir + (size_t)x1 * D))[lane];
    float4 y = ((const float4*)(hyb  + (size_t)x2 * D))[lane];
    ((float4*)g_h)[(size_t)node * 32 + lane] =
        make_float4(a.x + c.x + y.x, a.y + c.y + y.y,
                    a.z + c.z + y.z, a.w + c.w + y.w);
}

// ---------------- weight prep: transpose + bf16 split --------------------------
__global__ void wprep_kernel(const float* __restrict__ W1,
                             const float* __restrict__ W2) {
    int t = blockIdx.x * blockDim.x + threadIdx.x;
    int total = 5 * 128 * 256;
    if (t < total) {
        int l = t / (128 * 256);
        int r = t % (128 * 256);
        int k = r / 256, n = r % 256;
        float v = W1[t];
        __nv_bfloat16 h = __float2bfloat16(v);
        g_wt1_hi[l * 32768 + n * 128 + k] = h;
        g_wt1_lo[l * 32768 + n * 128 + k] =
            __float2bfloat16(v - __bfloat162float(h));
    } else if (t < 2 * total) {
        int u = t - total;
        int l = u / (256 * 128);
        int r = u % (256 * 128);
        int k = r / 128, n = r % 128;
        float v = W2[u];
        __nv_bfloat16 h = __float2bfloat16(v);
        g_wt2_hi[l * 32768 + n * 256 + k] = h;
        g_wt2_lo[l * 32768 + n * 256 + k] =
            __float2bfloat16(v - __bfloat162float(h));
    }
}

// ---------------- CSR build ----------------------------------------------------
__global__ void count_kernel(const int* __restrict__ ei) {
    int e = blockIdx.x * blockDim.x + threadIdx.x;
    if (e >= NE) return;
    atomicAdd(&g_cnt[ei[NE + e]], 1);
}

__global__ void scan_kernel() {
    __shared__ int warpsum[32];
    __shared__ int carry;
    int lane = threadIdx.x & 31, wid = threadIdx.x >> 5;
    if (threadIdx.x == 0) carry = 0;
    __syncthreads();
    for (int base = 0; base < NN; base += 1024) {
        int i = base + threadIdx.x;
        int v = (i < NN) ? g_cnt[i] : 0;
        int xs = v;
#pragma unroll
        for (int off = 1; off < 32; off <<= 1) {
            int t = __shfl_up_sync(0xffffffff, xs, off);
            if (lane >= off) xs += t;
        }
        if (lane == 31) warpsum[wid] = xs;
        __syncthreads();
        if (wid == 0) {
            int w = warpsum[lane];
#pragma unroll
            for (int off = 1; off < 32; off <<= 1) {
                int t = __shfl_up_sync(0xffffffff, w, off);
                if (lane >= off) w += t;
            }
            warpsum[lane] = w;
        }
        __syncthreads();
        int wpre = (wid > 0) ? warpsum[wid - 1] : 0;
        int incl = xs + wpre;
        int excl = incl - v + carry;
        if (i < NN) { g_rowstart[i] = excl; g_cursor[i] = excl; }
        __syncthreads();
        if (threadIdx.x == 1023) carry += incl;
        __syncthreads();
    }
    if (threadIdx.x == 0) g_rowstart[NN] = carry;
}

__global__ void fill_kernel(const int* __restrict__ ei,
                            const int* __restrict__ ea) {
    int e = blockIdx.x * blockDim.x + threadIdx.x;
    if (e >= NE) return;
    int dst = ei[NE + e];
    int pos = atomicAdd(&g_cursor[dst], 1);
    int cb = ea[2 * e] * 4 + ea[2 * e + 1];
    g_edges[pos] = ei[e] | (cb << 16);
}

// ---------------- edge-combo tables for ALL layers ------------------------------
__global__ void eec_kernel(const float* __restrict__ e1,
                           const float* __restrict__ e2) {
    int b = blockIdx.x;            // 0..119 = l*24+cb
    int l = b / 24, cb = b % 24;
    int lane = threadIdx.x;
    int a0 = cb >> 2, a1 = cb & 3;
    float4 v1 = ((const float4*)(e1 + (size_t)l * 6 * D + (size_t)a0 * D))[lane];
    float4 v2 = ((const float4*)(e2 + (size_t)l * 4 * D + (size_t)a1 * D))[lane];
    ((float4*)g_eec)[(l * 24 + cb) * 32 + lane] =
        make_float4(v1.x + v2.x, v1.y + v2.y, v1.z + v2.z, v1.w + v2.w);
}

// ---------------- zero stats (once at prep; bnprep re-zeros per layer) ----------
__global__ void zero_stats_kernel() {
    g_sum[threadIdx.x] = 0.f;
    g_sumsq[threadIdx.x] = 0.f;
}

// ---------------- gather-aggregate: warp per node, emits bf16 hi/lo -------------
__global__ void agg_kernel(const float* __restrict__ h, int layer) {
    int t = blockIdx.x * blockDim.x + threadIdx.x;
    int n = t >> 5, lane = t & 31;
    if (n >= NN) return;
    const float4* eec = ((const float4*)g_eec) + layer * 24 * 32;
    int beg = g_rowstart[n], end = g_rowstart[n + 1];
    float4 acc = make_float4(0.f, 0.f, 0.f, 0.f);
    int i = beg;
    for (; i + 3 < end; i += 4) {
        int p0 = g_edges[i];
        int p1 = g_edges[i + 1];
        int p2 = g_edges[i + 2];
        int p3 = g_edges[i + 3];
        float4 a0 = ((const float4*)h)[(size_t)(p0 & 0xFFFF) * 32 + lane];
        float4 a1 = ((const float4*)h)[(size_t)(p1 & 0xFFFF) * 32 + lane];
        float4 a2 = ((const float4*)h)[(size_t)(p2 & 0xFFFF) * 32 + lane];
        float4 a3 = ((const float4*)h)[(size_t)(p3 & 0xFFFF) * 32 + lane];
        float4 e0 = eec[(p0 >> 16) * 32 + lane];
        float4 e1v = eec[(p1 >> 16) * 32 + lane];
        float4 e2v = eec[(p2 >> 16) * 32 + lane];
        float4 e3v = eec[(p3 >> 16) * 32 + lane];
        acc.x += (a0.x + e0.x) + (a1.x + e1v.x) + (a2.x + e2v.x) + (a3.x + e3v.x);
        acc.y += (a0.y + e0.y) + (a1.y + e1v.y) + (a2.y + e2v.y) + (a3.y + e3v.y);
        acc.z += (a0.z + e0.z) + (a1.z + e1v.z) + (a2.z + e2v.z) + (a3.z + e3v.z);
        acc.w += (a0.w + e0.w) + (a1.w + e1v.w) + (a2.w + e2v.w) + (a3.w + e3v.w);
    }
    for (; i < end; ++i) {
        int p0 = g_edges[i];
        float4 a = ((const float4*)h)[(size_t)(p0 & 0xFFFF) * 32 + lane];
        float4 e0 = eec[(p0 >> 16) * 32 + lane];
        acc.x += a.x + e0.x;
        acc.y += a.y + e0.y;
        acc.z += a.z + e0.z;
        acc.w += a.w + e0.w;
    }
    uint32_t h0, l0, h1, l1;
    split2(acc.x, acc.y, h0, l0);
    split2(acc.z, acc.w, h1, l1);
    ((uint2*)g_agg_hi)[(size_t)n * 32 + lane] = make_uint2(h0, h1);
    ((uint2*)g_agg_lo)[(size_t)n * 32 + lane] = make_uint2(l0, l1);
}

// ---------------- BN prep (also re-zeros stats for next layer) ------------------
__global__ void bnprep_kernel(const float* __restrict__ gamma,
                              const float* __restrict__ beta) {
    int c = threadIdx.x;
    const float inv = 1.0f / (float)NN;
    float mean = g_sum[c] * inv;
    float var = g_sumsq[c] * inv - mean * mean;
    float s = gamma[c] * rsqrtf(var + BN_EPS);
    g_bns[c] = s;
    g_bnt[c] = beta[c] - mean * s;
    g_sum[c] = 0.f;
    g_sumsq[c] = 0.f;
}

__global__ void bn_apply_kernel(const float* __restrict__ h2,
                                float* __restrict__ outp, int relu) {
    int t = blockIdx.x * blockDim.x + threadIdx.x;
    int node = t >> 5, lane = t & 31;
    if (node >= NN) return;
    float4 s4 = ((const float4*)g_bns)[lane];
    float4 t4 = ((const float4*)g_bnt)[lane];
    float4 v = ((const float4*)h2)[(size_t)node * 32 + lane];
    float4 o = make_float4(fmaf(s4.x, v.x, t4.x), fmaf(s4.y, v.y, t4.y),
                           fmaf(s4.z, v.z, t4.z), fmaf(s4.w, v.w, t4.w));
    if (relu) {
        o.x = fmaxf(o.x, 0.f); o.y = fmaxf(o.y, 0.f);
        o.z = fmaxf(o.z, 0.f); o.w = fmaxf(o.w, 0.f);
    }
    ((float4*)outp)[(size_t)node * 32 + lane] = o;
}

// ---------------- bf16x3 tensor-core GEMM, cp.async double-buffered -------------
#define MMA_BF16(acc, a, b)                                              \
    asm volatile(                                                        \
        "mma.sync.aligned.m16n8k16.row.col.f32.bf16.bf16.f32 "           \
        "{%0,%1,%2,%3}, {%4,%5,%6,%7}, {%8,%9}, {%0,%1,%2,%3};\n"        \
        : "+f"(acc[0]), "+f"(acc[1]), "+f"(acc[2]), "+f"(acc[3])         \
        : "r"(a[0]), "r"(a[1]), "r"(a[2]), "r"(a[3]),                    \
          "r"(b[0]), "r"(b[1]))

#define PAD 40
#define TILE_E (128 * PAD)              // bf16 elems per tile
#define STAGE_E (4 * TILE_E)            // 4 tiles per stage
#define SMEM_BYTES (2 * STAGE_E * 2)    // 2 stages, 2B/elem = 81920

__global__ __launch_bounds__(256) void gemm_bf16x3_kernel(
    const __nv_bfloat16* __restrict__ Ah, const __nv_bfloat16* __restrict__ Al,
    const __nv_bfloat16* __restrict__ Bh, const __nv_bfloat16* __restrict__ Bl,
    const float* __restrict__ bias,
    float* __restrict__ Cf, __nv_bfloat16* __restrict__ Ch,
    __nv_bfloat16* __restrict__ Cl,
    int M, int N, int K, int relu, int do_stats, int out_bf16) {
    extern __shared__ __nv_bfloat16 smem[];

    const int tid  = threadIdx.x;
    const int warp = tid >> 5, lane = tid & 31;
    const int gid  = lane >> 2;
    const int tig  = lane & 3;
    const int wm   = (warp & 3) * 32;
    const int wn   = (warp >> 2) * 64;
    const int m0   = blockIdx.y * 128;
    const int n0b  = blockIdx.x * 128;

    float acc[2][8][4];
#pragma unroll
    for (int mi = 0; mi < 2; mi++)
#pragma unroll
        for (int ni = 0; ni < 8; ni++)
#pragma unroll
            for (int q = 0; q < 4; q++) acc[mi][ni][q] = 0.f;

    const int sr = tid >> 2;            // 0..63
    const int sc = (tid & 3) * 8;       // 16B = 8 bf16

    const int nchunk = K >> 5;          // BK=32

    auto stage = [&](int c) {
        __nv_bfloat16* buf = smem + (c & 1) * STAGE_E;
        __nv_bfloat16* Ah_s = buf;
        __nv_bfloat16* Al_s = buf + TILE_E;
        __nv_bfloat16* Bh_s = buf + 2 * TILE_E;
        __nv_bfloat16* Bl_s = buf + 3 * TILE_E;
        int k0 = c << 5;
#pragma unroll
        for (int i = 0; i < 2; i++) {
            int r = sr + i * 64;
            bool ok = (m0 + r < M);
            const __nv_bfloat16* sa = ok ? (Ah + (size_t)(m0 + r) * K + k0 + sc) : Ah;
            const __nv_bfloat16* sl = ok ? (Al + (size_t)(m0 + r) * K + k0 + sc) : Al;
            cp_async16(&Ah_s[r * PAD + sc], sa, ok ? 16 : 0);
            cp_async16(&Al_s[r * PAD + sc], sl, ok ? 16 : 0);
            cp_async16(&Bh_s[r * PAD + sc], Bh + (size_t)(n0b + r) * K + k0 + sc, 16);
            cp_async16(&Bl_s[r * PAD + sc], Bl + (size_t)(n0b + r) * K + k0 + sc, 16);
        }
        CP_COMMIT();
    };

    stage(0);

    for (int c = 0; c < nchunk; ++c) {
        if (c + 1 < nchunk) {
            stage(c + 1);
            CP_WAIT(1);
        } else {
            CP_WAIT(0);
        }
        __syncthreads();

        __nv_bfloat16* buf = smem + (c & 1) * STAGE_E;
        const __nv_bfloat16* Ah_s = buf;
        const __nv_bfloat16* Al_s = buf + TILE_E;
        const __nv_bfloat16* Bh_s = buf + 2 * TILE_E;
        const __nv_bfloat16* Bl_s = buf + 3 * TILE_E;

#pragma unroll
        for (int ks = 0; ks < 2; ks++) {
            const int kk = ks * 16;
            uint32_t ah[2][4], al[2][4], bh[8][2], bl[8][2];
#pragma unroll
            for (int mi = 0; mi < 2; mi++) {
                int r0 = wm + mi * 16 + gid;
                ah[mi][0] = *(const uint32_t*)&Ah_s[r0 * PAD + kk + tig * 2];
                ah[mi][1] = *(const uint32_t*)&Ah_s[(r0 + 8) * PAD + kk + tig * 2];
                ah[mi][2] = *(const uint32_t*)&Ah_s[r0 * PAD + kk + 8 + tig * 2];
                ah[mi][3] = *(const uint32_t*)&Ah_s[(r0 + 8) * PAD + kk + 8 + tig * 2];
                al[mi][0] = *(const uint32_t*)&Al_s[r0 * PAD + kk + tig * 2];
                al[mi][1] = *(const uint32_t*)&Al_s[(r0 + 8) * PAD + kk + tig * 2];
                al[mi][2] = *(const uint32_t*)&Al_s[r0 * PAD + kk + 8 + tig * 2];
                al[mi][3] = *(const uint32_t*)&Al_s[(r0 + 8) * PAD + kk + 8 + tig * 2];
            }
#pragma unroll
            for (int ni = 0; ni < 8; ni++) {
                int c0 = wn + ni * 8 + gid;
                bh[ni][0] = *(const uint32_t*)&Bh_s[c0 * PAD + kk + tig * 2];
                bh[ni][1] = *(const uint32_t*)&Bh_s[c0 * PAD + kk + 8 + tig * 2];
                bl[ni][0] = *(const uint32_t*)&Bl_s[c0 * PAD + kk + tig * 2];
                bl[ni][1] = *(const uint32_t*)&Bl_s[c0 * PAD + kk + 8 + tig * 2];
            }
#pragma unroll
            for (int mi = 0; mi < 2; mi++)
#pragma unroll
                for (int ni = 0; ni < 8; ni++) {
                    MMA_BF16(acc[mi][ni], al[mi], bh[ni]);
                    MMA_BF16(acc[mi][ni], ah[mi], bl[ni]);
                    MMA_BF16(acc[mi][ni], ah[mi], bh[ni]);
                }
        }
        __syncthreads();
    }

    // epilogue
    float ls[16], ls2[16];
#pragma unroll
    for (int j = 0; j < 16; j++) { ls[j] = 0.f; ls2[j] = 0.f; }

#pragma unroll
    for (int mi = 0; mi < 2; mi++) {
        int r0 = m0 + wm + mi * 16 + gid;
#pragma unroll
        for (int ni = 0; ni < 8; ni++) {
            int gc = n0b + wn + ni * 8 + 2 * tig;
            float bv0 = bias[gc], bv1 = bias[gc + 1];
            float v0 = acc[mi][ni][0] + bv0;
            float v1 = acc[mi][ni][1] + bv1;
            float v2 = acc[mi][ni][2] + bv0;
            float v3 = acc[mi][ni][3] + bv1;
            if (relu) {
                v0 = fmaxf(v0, 0.f); v1 = fmaxf(v1, 0.f);
                v2 = fmaxf(v2, 0.f); v3 = fmaxf(v3, 0.f);
            }
            bool ok0 = (r0 < M), ok1 = (r0 + 8 < M);
            if (out_bf16) {
                uint32_t h0, l0, h1, l1;
                split2(v0, v1, h0, l0);
                split2(v2, v3, h1, l1);
                if (ok0) {
                    *(uint32_t*)(Ch + (size_t)r0 * N + gc) = h0;
                    *(uint32_t*)(Cl + (size_t)r0 * N + gc) = l0;
                }
                if (ok1) {
                    *(uint32_t*)(Ch + (size_t)(r0 + 8) * N + gc) = h1;
                    *(uint32_t*)(Cl + (size_t)(r0 + 8) * N + gc) = l1;
                }
            } else {
                if (ok0)
                    *(float2*)(Cf + (size_t)r0 * N + gc) = make_float2(v0, v1);
                if (ok1)
                    *(float2*)(Cf + (size_t)(r0 + 8) * N + gc) = make_float2(v2, v3);
            }
            if (do_stats) {
                if (ok0) {
                    ls[ni * 2]     += v0; ls2[ni * 2]     += v0 * v0;
                    ls[ni * 2 + 1] += v1; ls2[ni * 2 + 1] += v1 * v1;
                }
                if (ok1) {
                    ls[ni * 2]     += v2; ls2[ni * 2]     += v2 * v2;
                    ls[ni * 2 + 1] += v3; ls2[ni * 2 + 1] += v3 * v3;
                }
            }
        }
    }

    if (do_stats) {
#pragma unroll
        for (int j = 0; j < 16; j++) {
#pragma unroll
            for (int off = 4; off < 32; off <<= 1) {
                ls[j]  += __shfl_xor_sync(0xffffffff, ls[j], off);
                ls2[j] += __shfl_xor_sync(0xffffffff, ls2[j], off);
            }
        }
        float* cs  = (float*)smem;
        float* cs2 = (float*)smem + 128;
        if (tid < 128) { cs[tid] = 0.f; cs2[tid] = 0.f; }
        __syncthreads();
        if (lane < 4) {
#pragma unroll
            for (int ni = 0; ni < 8; ni++) {
                int c0 = wn + ni * 8 + 2 * lane;
                atomicAdd(&cs[c0],      ls[ni * 2]);
                atomicAdd(&cs2[c0],     ls2[ni * 2]);
                atomicAdd(&cs[c0 + 1],  ls[ni * 2 + 1]);
                atomicAdd(&cs2[c0 + 1], ls2[ni * 2 + 1]);
            }
        }
        __syncthreads();
        if (tid < 128) {
            atomicAdd(&g_sum[tid],   cs[tid]);
            atomicAdd(&g_sumsq[tid], cs2[tid]);
        }
    }
}

// ---------------- launch --------------------------------------------------------
extern "C" void kernel_launch(void* const* d_in, const int* in_sizes, int n_in,
                              void* d_out, int out_size) {
    const int*   x     = (const int*)d_in[0];
    const int*   ei    = (const int*)d_in[1];
    const int*   ea    = (const int*)d_in[2];
    const float* atom  = (const float*)d_in[3];
    const float* chir  = (const float*)d_in[4];
    const float* hyb   = (const float*)d_in[5];
    const float* e1    = (const float*)d_in[6];
    const float* e2    = (const float*)d_in[7];
    const float* W1    = (const float*)d_in[8];
    const float* b1    = (const float*)d_in[9];
    const float* W2    = (const float*)d_in[10];
    const float* b2    = (const float*)d_in[11];
    const float* gamma = (const float*)d_in[12];
    const float* beta  = (const float*)d_in[13];
    float* out = (float*)d_out;

    float *p_h, *p_h2;
    int* p_cnt;
    __nv_bfloat16 *p_agg_hi, *p_agg_lo, *p_mid_hi, *p_mid_lo;
    __nv_bfloat16 *p_wt1_hi, *p_wt1_lo, *p_wt2_hi, *p_wt2_lo;
    cudaGetSymbolAddress((void**)&p_h,      g_h);
    cudaGetSymbolAddress((void**)&p_h2,     g_h2);
    cudaGetSymbolAddress((void**)&p_cnt,    g_cnt);
    cudaGetSymbolAddress((void**)&p_agg_hi, g_agg_hi);
    cudaGetSymbolAddress((void**)&p_agg_lo, g_agg_lo);
    cudaGetSymbolAddress((void**)&p_mid_hi, g_mid_hi);
    cudaGetSymbolAddress((void**)&p_mid_lo, g_mid_lo);
    cudaGetSymbolAddress((void**)&p_wt1_hi, g_wt1_hi);
    cudaGetSymbolAddress((void**)&p_wt1_lo, g_wt1_lo);
    cudaGetSymbolAddress((void**)&p_wt2_hi, g_wt2_hi);
    cudaGetSymbolAddress((void**)&p_wt2_lo, g_wt2_lo);

    cudaFuncSetAttribute(gemm_bf16x3_kernel,
                         cudaFuncAttributeMaxDynamicSharedMemorySize,
                         SMEM_BYTES);

    const int TPB = 256;
    const int node_blocks = (NN * 32 + TPB - 1) / TPB;
    const int edge_blocks = (NE + TPB - 1) / TPB;
    const int mrows = (NN + 127) / 128;

    // one-time prep (layer-invariant)
    cudaMemsetAsync(p_cnt, 0, NN * sizeof(int));
    zero_stats_kernel<<<1, 128>>>();
    count_kernel<<<edge_blocks, TPB>>>(ei);
    scan_kernel<<<1, 1024>>>();
    fill_kernel<<<edge_blocks, TPB>>>(ei, ea);
    wprep_kernel<<<(2 * 5 * 128 * 256 + TPB - 1) / TPB, TPB>>>(W1, W2);
    eec_kernel<<<120, 32>>>(e1, e2);
    embed_kernel<<<node_blocks, TPB>>>(x, atom, chir, hyb);

    for (int l = 0; l < 5; ++l) {
        agg_kernel<<<node_blocks, TPB>>>(p_h, l);
        // Linear1 + ReLU -> mid (bf16 hi/lo)
        gemm_bf16x3_kernel<<<dim3(2, mrows), 256, SMEM_BYTES>>>(
            p_agg_hi, p_agg_lo,
            p_wt1_hi + (size_t)l * 32768, p_wt1_lo + (size_t)l * 32768,
            b1 + (size_t)l * 2 * D,
            nullptr, p_mid_hi, p_mid_lo,
            NN, 2 * D, D, 1, 0, 1);
        // Linear2 -> h2 (fp32) with fused column stats
        gemm_bf16x3_kernel<<<dim3(1, mrows), 256, SMEM_BYTES>>>(
            p_mid_hi, p_mid_lo,
            p_wt2_hi + (size_t)l * 32768, p_wt2_lo + (size_t)l * 32768,
            b2 + (size_t)l * D,
            p_h2, nullptr, nullptr,
            NN, D, 2 * D, 0, 1, 0);
        bnprep_kernel<<<1, 128>>>(gamma + (size_t)l * D, beta + (size_t)l * D);
        bn_apply_kernel<<<node_blocks, TPB>>>(p_h2, (l == 4) ? out : p_h,
                                              (l < 4) ? 1 : 0);
    }
}